// round 5
// baseline (speedup 1.0000x reference)
#include <cuda_runtime.h>
#include <cfloat>

#define NCOLS 1000
#define NVEC  250          // float4s per row per array
#define TPB   32
#define NCHUNK 8           // 8 * 32 = 256 >= 250
#define TAIL_VALID (NVEC - 7 * TPB)   // 26

// Order-preserving float<->uint mapping
__device__ __forceinline__ unsigned ford(float f) {
    unsigned u = __float_as_uint(f);
    return ((int)u < 0) ? ~u : (u | 0x80000000u);
}
__device__ __forceinline__ float funord(unsigned u) {
    return __uint_as_float(((int)u < 0) ? (u ^ 0x80000000u) : ~u);
}

// Exact warp top-2 in ordered-uint domain (per-lane o1 >= o2 on entry).
__device__ __forceinline__ void warp_top2(unsigned& o1, unsigned& o2) {
    unsigned r1  = __reduce_max_sync(0xFFFFFFFFu, o1);
    unsigned bal = __ballot_sync(0xFFFFFFFFu, o1 == r1);
    unsigned u   = (o1 == r1) ? o2 : o1;
    unsigned r2  = __reduce_max_sync(0xFFFFFFFFu, u);
    if (__popc(bal) > 1) r2 = r1;   // duplicated max across lanes -> t2 == t1
    o1 = r1; o2 = r2;
}

// Branchless exact top-2 of 8 (FMNMX tournament)
__device__ __forceinline__ void top2_8(const float* v, float& t1, float& t2) {
    float m0 = fmaxf(v[0], v[1]), n0 = fminf(v[0], v[1]);
    float m1 = fmaxf(v[2], v[3]), n1 = fminf(v[2], v[3]);
    float m2 = fmaxf(v[4], v[5]), n2 = fminf(v[4], v[5]);
    float m3 = fmaxf(v[6], v[7]), n3 = fminf(v[6], v[7]);
    float a1 = fmaxf(m0, m1), a2 = fmaxf(fminf(m0, m1), fmaxf(n0, n1));
    float b1 = fmaxf(m2, m3), b2 = fmaxf(fminf(m2, m3), fmaxf(n2, n3));
    t1 = fmaxf(a1, b1);
    t2 = fmaxf(fminf(a1, b1), fmaxf(a2, b2));
}

// Merge (t1,t2) <- top2 of union with (q1,q2)
__device__ __forceinline__ void pair_merge(float& t1, float& t2, float q1, float q2) {
    float mn = fminf(t1, q1);
    t1 = fmaxf(t1, q1);
    t2 = fmaxf(mn, fmaxf(t2, q2));
}

// Exact top-2 of 32 values
__device__ __forceinline__ void top2_32(const float* v, float& t1, float& t2) {
    float p1, p2, q1, q2, r1, r2, s1, s2;
    top2_8(v,      p1, p2);
    top2_8(v + 8,  q1, q2);
    top2_8(v + 16, r1, r2);
    top2_8(v + 24, s1, s2);
    pair_merge(p1, p2, q1, q2);
    pair_merge(r1, r2, s1, s2);
    pair_merge(p1, p2, r1, r2);
    t1 = p1; t2 = p2;
}

__global__ __launch_bounds__(TPB)
void netsat1_kernel(const float* __restrict__ y1,
                    const float* __restrict__ y2,
                    float* __restrict__ out)
{
    const int row = blockIdx.x;
    const int t   = threadIdx.x;

    const float4* r1 = reinterpret_cast<const float4*>(y1 + (size_t)row * NCOLS);
    const float4* r2 = reinterpret_cast<const float4*>(y2 + (size_t)row * NCOLS);

    // 8 chunks per array, all loads unconditional (tail clamped + lane-masked)
    const bool tv   = (t < TAIL_VALID);
    const int  idx7 = tv ? (7 * TPB + t) : t;   // safe duplicate, masked below

    float a[32], b[32];
    float4 va[NCHUNK], vb[NCHUNK];
    #pragma unroll
    for (int c = 0; c < 7; ++c) {
        va[c] = __ldg(&r1[t + c * TPB]);
        vb[c] = __ldg(&r2[t + c * TPB]);
    }
    va[7] = __ldg(&r1[idx7]);
    vb[7] = __ldg(&r2[idx7]);

    #pragma unroll
    for (int c = 0; c < 7; ++c) {
        a[4*c+0]=va[c].x; a[4*c+1]=va[c].y; a[4*c+2]=va[c].z; a[4*c+3]=va[c].w;
        b[4*c+0]=vb[c].x; b[4*c+1]=vb[c].y; b[4*c+2]=vb[c].z; b[4*c+3]=vb[c].w;
    }
    a[28] = tv ? va[7].x : -FLT_MAX;  a[29] = tv ? va[7].y : -FLT_MAX;
    a[30] = tv ? va[7].z : -FLT_MAX;  a[31] = tv ? va[7].w : -FLT_MAX;
    b[28] = tv ? vb[7].x : -FLT_MAX;  b[29] = tv ? vb[7].y : -FLT_MAX;
    b[30] = tv ? vb[7].z : -FLT_MAX;  b[31] = tv ? vb[7].w : -FLT_MAX;

    // --- Pass 1: per-thread exact top-2 of 32, then warp top-2 (row-wide) ---
    float ta1, ta2, tb1, tb2;
    top2_32(a, ta1, ta2);
    top2_32(b, tb1, tb2);

    unsigned oa1 = ford(ta1), oa2 = ford(ta2);
    unsigned ob1 = ford(tb1), ob2 = ford(tb2);
    warp_top2(oa1, oa2);
    warp_top2(ob1, ob2);

    const float t1_1 = funord(oa1), t2_1 = funord(oa2);
    const float t1_2 = funord(ob1), t2_2 = funord(ob2);

    // --- Pass 2 (registers), shifted domain:
    // min(y1-t1_1, y2-t1_2) = min(y1, y2 + d) - t1_1,  d = t1_1 - t1_2
    const float d = t1_1 - t1_2;
    float m = -FLT_MAX;
    #pragma unroll
    for (int k = 0; k < 32; ++k)
        m = fmaxf(m, fminf(a[k], b[k] + d));

    // Fixup iff this thread holds a row-argmax element of either array (1-2 lanes).
    if ((ta1 == t1_1) || (tb1 == t1_2)) {
        #pragma unroll
        for (int k = 0; k < 32; ++k) {
            if (a[k] == t1_1 || b[k] == t1_2) {
                float loo1 = (a[k] == t1_1) ? t2_1 : t1_1;
                float loo2 = (b[k] == t1_2) ? t2_2 : t1_2;
                m = fmaxf(m, fminf(a[k] - loo1, b[k] - loo2) + t1_1);  // shifted
            }
        }
    }

    // --- Warp max reduce of m, lane 0 writes ---
    unsigned om = __reduce_max_sync(0xFFFFFFFFu, ford(m));
    if (t == 0)
        out[row] = funord(om) - t1_1;   // un-shift
}

extern "C" void kernel_launch(void* const* d_in, const int* in_sizes, int n_in,
                              void* d_out, int out_size)
{
    const float* y1 = (const float*)d_in[0];
    const float* y2 = (const float*)d_in[1];
    float* out = (float*)d_out;

    const int B = in_sizes[0] / NCOLS;   // 16384
    netsat1_kernel<<<B, TPB>>>(y1, y2, out);
}

// round 6
// speedup vs baseline: 1.0094x; 1.0094x over previous
#include <cuda_runtime.h>
#include <cfloat>
#include <cstdint>

#define NCOLS 1000
#define TPB   64
#define NWARP 2
#define ROW_BYTES 4000        // NCOLS * 4, multiple of 16

// Order-preserving float<->uint mapping
__device__ __forceinline__ unsigned ford(float f) {
    unsigned u = __float_as_uint(f);
    return ((int)u < 0) ? ~u : (u | 0x80000000u);
}
__device__ __forceinline__ float funord(unsigned u) {
    return __uint_as_float(((int)u < 0) ? (u ^ 0x80000000u) : ~u);
}

__device__ __forceinline__ uint32_t smem_u32(const void* p) {
    uint32_t a;
    asm("{ .reg .u64 t; cvta.to.shared.u64 t, %1; cvt.u32.u64 %0, t; }" : "=r"(a) : "l"(p));
    return a;
}

// Exact warp top-2 in ordered-uint domain (per-lane o1 >= o2 on entry).
__device__ __forceinline__ void warp_top2(unsigned& o1, unsigned& o2) {
    unsigned r1  = __reduce_max_sync(0xFFFFFFFFu, o1);
    unsigned bal = __ballot_sync(0xFFFFFFFFu, o1 == r1);
    unsigned u   = (o1 == r1) ? o2 : o1;
    unsigned r2  = __reduce_max_sync(0xFFFFFFFFu, u);
    if (__popc(bal) > 1) r2 = r1;   // duplicated max across lanes -> t2 == t1
    o1 = r1; o2 = r2;
}

// Branchless exact top-2 of 8 (FMNMX tournament)
__device__ __forceinline__ void top2_8(const float* v, float& t1, float& t2) {
    float m0 = fmaxf(v[0], v[1]), n0 = fminf(v[0], v[1]);
    float m1 = fmaxf(v[2], v[3]), n1 = fminf(v[2], v[3]);
    float m2 = fmaxf(v[4], v[5]), n2 = fminf(v[4], v[5]);
    float m3 = fmaxf(v[6], v[7]), n3 = fminf(v[6], v[7]);
    float a1 = fmaxf(m0, m1), a2 = fmaxf(fminf(m0, m1), fmaxf(n0, n1));
    float b1 = fmaxf(m2, m3), b2 = fmaxf(fminf(m2, m3), fmaxf(n2, n3));
    t1 = fmaxf(a1, b1);
    t2 = fmaxf(fminf(a1, b1), fmaxf(a2, b2));
}

// Merge (t1,t2) <- top2 of union with (q1,q2)
__device__ __forceinline__ void pair_merge(float& t1, float& t2, float q1, float q2) {
    float mn = fminf(t1, q1);
    t1 = fmaxf(t1, q1);
    t2 = fmaxf(mn, fmaxf(t2, q2));
}

__device__ __forceinline__ void top2_16v(const float4 c[4], float& t1, float& t2) {
    float v[16];
    #pragma unroll
    for (int i = 0; i < 4; ++i) {
        v[4*i+0] = c[i].x; v[4*i+1] = c[i].y; v[4*i+2] = c[i].z; v[4*i+3] = c[i].w;
    }
    float p1, p2, q1, q2;
    top2_8(v, p1, p2);
    top2_8(v + 8, q1, q2);
    pair_merge(p1, p2, q1, q2);
    t1 = p1; t2 = p2;
}

__global__ __launch_bounds__(TPB)
void netsat1_kernel(const float* __restrict__ y1,
                    const float* __restrict__ y2,
                    float* __restrict__ out)
{
    __shared__ alignas(16) float sa[1024];        // 4096 B (row + pad)
    __shared__ alignas(16) float sb[1024];
    __shared__ alignas(8)  unsigned long long mbar;
    __shared__ float4   sw[NWARP];
    __shared__ unsigned smax[NWARP];

    const int row = blockIdx.x;
    const int t   = threadIdx.x;
    const int wid = t >> 5;
    const int lid = t & 31;

    // Pad tail so all LDS are unconditional
    if (t < 24) { sa[1000 + t] = -FLT_MAX; sb[1000 + t] = -FLT_MAX; }

    const uint32_t mbar_a = smem_u32(&mbar);
    const uint32_t sa_a   = smem_u32(sa);
    const uint32_t sb_a   = smem_u32(sb);

    if (t == 0) {
        asm volatile("mbarrier.init.shared.b64 [%0], %1;" :: "r"(mbar_a), "r"(1) : "memory");
        asm volatile("fence.proxy.async.shared::cta;" ::: "memory");
    }
    __syncthreads();

    if (t == 0) {
        asm volatile("mbarrier.arrive.expect_tx.shared.b64 _, [%0], %1;"
                     :: "r"(mbar_a), "r"(2 * ROW_BYTES) : "memory");
        const float* src1 = y1 + (size_t)row * NCOLS;
        const float* src2 = y2 + (size_t)row * NCOLS;
        asm volatile("cp.async.bulk.shared::cluster.global.mbarrier::complete_tx::bytes [%0], [%1], %2, [%3];"
                     :: "r"(sa_a), "l"(src1), "r"(ROW_BYTES), "r"(mbar_a) : "memory");
        asm volatile("cp.async.bulk.shared::cluster.global.mbarrier::complete_tx::bytes [%0], [%1], %2, [%3];"
                     :: "r"(sb_a), "l"(src2), "r"(ROW_BYTES), "r"(mbar_a) : "memory");
    }

    // Wait (acquire) for both rows, parity 0
    {
        uint32_t done;
        asm volatile(
            "{\n\t"
            ".reg .pred p;\n\t"
            "mbarrier.try_wait.parity.acquire.cta.shared::cta.b64 p, [%1], %2;\n\t"
            "selp.b32 %0, 1, 0, p;\n\t"
            "}"
            : "=r"(done) : "r"(mbar_a), "r"(0) : "memory");
        if (!done) {
            asm volatile(
                "{\n\t"
                ".reg .pred P1;\n\t"
                "WAIT_LOOP:\n\t"
                "mbarrier.try_wait.parity.acquire.cta.shared::cta.b64 P1, [%0], %1, 0x989680;\n\t"
                "@P1 bra.uni WAIT_DONE;\n\t"
                "bra.uni WAIT_LOOP;\n\t"
                "WAIT_DONE:\n\t"
                "}"
                :: "r"(mbar_a), "r"(0) : "memory");
        }
    }

    const float4* av = reinterpret_cast<const float4*>(sa);
    const float4* bv = reinterpret_cast<const float4*>(sb);

    // --- Pass 1: per-thread top-2 of 16 per array (from smem), then warp top-2 ---
    float4 ca[4], cb[4];
    #pragma unroll
    for (int c = 0; c < 4; ++c) { ca[c] = av[t + c * TPB]; cb[c] = bv[t + c * TPB]; }

    float ta1, ta2, tb1, tb2;
    top2_16v(ca, ta1, ta2);
    top2_16v(cb, tb1, tb2);

    unsigned oa1 = ford(ta1), oa2 = ford(ta2);
    unsigned ob1 = ford(tb1), ob2 = ford(tb2);
    warp_top2(oa1, oa2);
    warp_top2(ob1, ob2);

    if (lid == 0)
        sw[wid] = make_float4(funord(oa1), funord(oa2), funord(ob1), funord(ob2));
    __syncthreads();

    float4 s0 = sw[0], s1 = sw[1];
    float t1_1 = s0.x, t2_1 = s0.y, t1_2 = s0.z, t2_2 = s0.w;
    pair_merge(t1_1, t2_1, s1.x, s1.y);
    pair_merge(t1_2, t2_2, s1.z, s1.w);

    // --- Pass 2 (re-read smem), shifted domain:
    // min(y1-t1_1, y2-t1_2) = min(y1, y2 + d) - t1_1,  d = t1_1 - t1_2
    const float d = t1_1 - t1_2;
    float m = -FLT_MAX;
    #pragma unroll
    for (int c = 0; c < 4; ++c) {
        float4 a4 = av[t + c * TPB];
        float4 b4 = bv[t + c * TPB];
        m = fmaxf(m, fminf(a4.x, b4.x + d));
        m = fmaxf(m, fminf(a4.y, b4.y + d));
        m = fmaxf(m, fminf(a4.z, b4.z + d));
        m = fmaxf(m, fminf(a4.w, b4.w + d));
    }

    // Fixup iff this thread holds a row-argmax element of either array (cold).
    if ((ta1 == t1_1) || (tb1 == t1_2)) {
        #pragma unroll
        for (int c = 0; c < 4; ++c) {
            float4 a4 = av[t + c * TPB];
            float4 b4 = bv[t + c * TPB];
            float aa[4] = {a4.x, a4.y, a4.z, a4.w};
            float bb[4] = {b4.x, b4.y, b4.z, b4.w};
            #pragma unroll
            for (int k = 0; k < 4; ++k) {
                if (aa[k] == t1_1 || bb[k] == t1_2) {
                    float loo1 = (aa[k] == t1_1) ? t2_1 : t1_1;
                    float loo2 = (bb[k] == t1_2) ? t2_2 : t1_2;
                    m = fmaxf(m, fminf(aa[k] - loo1, bb[k] - loo2) + t1_1);  // shifted
                }
            }
        }
    }

    // --- Block max reduce (2 warps) ---
    unsigned om = __reduce_max_sync(0xFFFFFFFFu, ford(m));
    if (lid == 0) smax[wid] = om;
    __syncthreads();
    if (t == 0)
        out[row] = funord(max(smax[0], smax[1])) - t1_1;   // un-shift
}

extern "C" void kernel_launch(void* const* d_in, const int* in_sizes, int n_in,
                              void* d_out, int out_size)
{
    const float* y1 = (const float*)d_in[0];
    const float* y2 = (const float*)d_in[1];
    float* out = (float*)d_out;

    const int B = in_sizes[0] / NCOLS;   // 16384
    netsat1_kernel<<<B, TPB>>>(y1, y2, out);
}